// round 14
// baseline (speedup 1.0000x reference)
#include <cuda_runtime.h>
#include <cuda_fp16.h>
#include <math.h>
#include <stdint.h>

#define Bb_ 2
#define Ss_ 2048
#define Hh_ 2048
#define NH_ 16
#define NKV_ 4
#define HD_ 128
#define MTOK (Bb_ * Ss_)   // 4096 tokens

// Scratch (allocation-free rule: __device__ globals)
// pre-rope q/k now fp16
__device__ __half g_qp16[(size_t)MTOK * NH_ * HD_];
__device__ __half g_kp16[(size_t)MTOK * NKV_ * HD_];
// fp16 GEMM operands (single-rounded)
__device__ __half g_hs16[(size_t)MTOK * Hh_];
__device__ __half g_wq16[(size_t)NH_ * HD_ * Hh_];
__device__ __half g_wk16[(size_t)NKV_ * HD_ * Hh_];
__device__ __half g_wv16[(size_t)NKV_ * HD_ * Hh_];
// attention inputs (fp16, single)
__device__ __half g_q16[(size_t)MTOK * NH_ * HD_];
__device__ __half g_k16[(size_t)MTOK * NKV_ * HD_];
__device__ __half g_v16[(size_t)MTOK * NKV_ * HD_];
// O-proj operands (fp16 1-pass)
__device__ __half g_wo16[(size_t)Hh_ * NH_ * HD_];
__device__ __half g_a16[(size_t)MTOK * NH_ * HD_];

// ============================ helpers =======================================
__device__ __forceinline__ uint32_t smem_u32(const void* p) {
  uint32_t a;
  asm("{ .reg .u64 t; cvta.to.shared.u64 t, %1; cvt.u32.u64 %0, t; }"
      : "=r"(a) : "l"(p));
  return a;
}
__device__ __forceinline__ void cp16(uint32_t dst, const void* src) {
  asm volatile("cp.async.cg.shared.global [%0], [%1], 16;"
               :: "r"(dst), "l"(src));
}
__device__ __forceinline__ void cp_commit() {
  asm volatile("cp.async.commit_group;" ::: "memory");
}
__device__ __forceinline__ void cp_wait1() {
  asm volatile("cp.async.wait_group 1;" ::: "memory");
}
__device__ __forceinline__ void cp_wait0() {
  asm volatile("cp.async.wait_group 0;" ::: "memory");
}
__device__ __forceinline__ void ldsm4(uint32_t addr, uint32_t r[4]) {
  asm volatile("ldmatrix.sync.aligned.m8n8.x4.shared.b16 {%0,%1,%2,%3}, [%4];"
               : "=r"(r[0]), "=r"(r[1]), "=r"(r[2]), "=r"(r[3]) : "r"(addr));
}
__device__ __forceinline__ void ldsm4t(uint32_t addr, uint32_t r[4]) {
  asm volatile(
      "ldmatrix.sync.aligned.m8n8.x4.trans.shared.b16 {%0,%1,%2,%3}, [%4];"
      : "=r"(r[0]), "=r"(r[1]), "=r"(r[2]), "=r"(r[3]) : "r"(addr));
}
__device__ __forceinline__ void mmaf16(float c[4], const uint32_t a[4],
                                       uint32_t b0, uint32_t b1) {
  asm volatile(
      "mma.sync.aligned.m16n8k16.row.col.f32.f16.f16.f32 "
      "{%0,%1,%2,%3}, {%4,%5,%6,%7}, {%8,%9}, {%0,%1,%2,%3};"
      : "+f"(c[0]), "+f"(c[1]), "+f"(c[2]), "+f"(c[3])
      : "r"(a[0]), "r"(a[1]), "r"(a[2]), "r"(a[3]), "r"(b0), "r"(b1));
}

// ============================ prep kernel (merged) ==========================
#define N4_HS (MTOK * Hh_ / 4)            // 2M
#define N4_WQ (NH_ * HD_ * Hh_ / 4)       // 1M
#define N4_WKV (NKV_ * HD_ * Hh_ / 4)     // 256K
#define N4_TOT (N4_HS + N4_WQ + 2 * N4_WKV + N4_WQ)

__global__ __launch_bounds__(256) void round_all(
    const float* __restrict__ hs, const float* __restrict__ wq,
    const float* __restrict__ wk, const float* __restrict__ wv,
    const float* __restrict__ wo) {
  int i = blockIdx.x * blockDim.x + threadIdx.x;
  if (i >= N4_TOT) return;
  const float* src;
  __half* dst;
  int off;
  if (i < N4_HS) {
    src = hs; dst = g_hs16; off = i;
  } else if (i < N4_HS + N4_WQ) {
    src = wq; dst = g_wq16; off = i - N4_HS;
  } else if (i < N4_HS + N4_WQ + N4_WKV) {
    src = wk; dst = g_wk16; off = i - N4_HS - N4_WQ;
  } else if (i < N4_HS + N4_WQ + 2 * N4_WKV) {
    src = wv; dst = g_wv16; off = i - N4_HS - N4_WQ - N4_WKV;
  } else {
    src = wo; dst = g_wo16; off = i - N4_HS - N4_WQ - 2 * N4_WKV;
  }
  float4 v = ((const float4*)src)[off];
  __half2 a = __float22half2_rn(make_float2(v.x, v.y));
  __half2 b = __float22half2_rn(make_float2(v.z, v.w));
  ((uint2*)dst)[off] = make_uint2(*reinterpret_cast<uint32_t*>(&a),
                                  *reinterpret_cast<uint32_t*>(&b));
}

// ============ fp16 1-pass GEMM, cp.async 3-stage, 512 threads ===============
#define A_MAT (128 * 80)            // 10240 B
#define B_MAT (256 * 80)            // 20480 B
#define STG (A_MAT + B_MAT)         // 30720 B
#define GSM (3 * STG)               // 92160 B
#define KDIM 2048

// mode 0: fused QKV (bn<8 Q fp16, 8..9 K fp16, 10..11 V fp16)
// mode 1: O proj (A = g_a16, B = g_wo16, C = outC fp32)
__global__ __launch_bounds__(512, 1) void gemm_f16(int mode, float* outC) {
  extern __shared__ char sm[];
  const uint32_t smb = smem_u32(sm);
  const int tid = threadIdx.x, wid = tid >> 5, lane = tid & 31;
  const int wm = wid & 1, wn = wid >> 1;
  const int bn = blockIdx.x, bm = blockIdx.y;
  const int i4 = lane >> 3, j8 = lane & 7;

  const __half *Ab, *Bb;
  __half* H16;
  int colbase, N16, dest;  // 0..2 = fp16 out (Q/K/V), 3 = fp32 out
  if (mode == 0) {
    Ab = g_hs16 + (size_t)(bm * 128) * KDIM;
    if (bn < 8) {
      Bb = g_wq16 + (size_t)(bn * 256) * KDIM;
      colbase = bn * 256; dest = 0; H16 = g_qp16; N16 = 2048;
    } else if (bn < 10) {
      Bb = g_wk16 + (size_t)((bn - 8) * 256) * KDIM;
      colbase = (bn - 8) * 256; dest = 1; H16 = g_kp16; N16 = 512;
    } else {
      Bb = g_wv16 + (size_t)((bn - 10) * 256) * KDIM;
      colbase = (bn - 10) * 256; dest = 2; H16 = g_v16; N16 = 512;
    }
  } else {
    Ab = g_a16 + (size_t)(bm * 128) * KDIM;
    Bb = g_wo16 + (size_t)(bn * 256) * KDIM;
    colbase = bn * 256; dest = 3; H16 = nullptr; N16 = 2048;
  }

  float ac[4][4][4];
#pragma unroll
  for (int mt = 0; mt < 4; mt++)
#pragma unroll
    for (int nt = 0; nt < 4; nt++)
#pragma unroll
      for (int q = 0; q < 4; q++) ac[mt][nt][q] = 0.f;

  auto issue = [&](int s, int k0) {
    const uint32_t st = smb + s * STG;
    {
      int r = tid >> 2, c = tid & 3;
      size_t go = (size_t)r * KDIM + k0 + c * 8;
      uint32_t so = (uint32_t)(r * 80 + c * 16);
      cp16(st + so, Ab + go);
    }
#pragma unroll
    for (int i = 0; i < 2; i++) {
      int e = i * 512 + tid;
      int r = e >> 2, c = e & 3;
      size_t go = (size_t)r * KDIM + k0 + c * 8;
      uint32_t so = (uint32_t)(r * 80 + c * 16);
      cp16(st + A_MAT + so, Bb + go);
    }
  };

  auto compute = [&](int s) {
    const uint32_t base = smb + s * STG;
#pragma unroll
    for (int ks = 0; ks < 2; ks++) {
      uint32_t af[4][4];
#pragma unroll
      for (int mt = 0; mt < 4; mt++) {
        uint32_t addr = base +
                        (uint32_t)(wm * 64 + mt * 16 + (i4 & 1) * 8 + j8) * 80 +
                        (uint32_t)((i4 >> 1) * 8 + ks * 16) * 2;
        ldsm4(addr, af[mt]);
      }
      uint32_t bf[4][2];
#pragma unroll
      for (int p = 0; p < 2; p++) {
        uint32_t r[4];
        uint32_t addr = base + A_MAT +
                        (uint32_t)(wn * 32 + p * 16 + (i4 >> 1) * 8 + j8) * 80 +
                        (uint32_t)((i4 & 1) * 8 + ks * 16) * 2;
        ldsm4(addr, r);
        bf[2 * p][0] = r[0]; bf[2 * p][1] = r[1];
        bf[2 * p + 1][0] = r[2]; bf[2 * p + 1][1] = r[3];
      }
#pragma unroll
      for (int mt = 0; mt < 4; mt++)
#pragma unroll
        for (int nt = 0; nt < 4; nt++)
          mmaf16(ac[mt][nt], af[mt], bf[nt][0], bf[nt][1]);
    }
  };

  const int KS = KDIM >> 5;  // 64
  issue(0, 0); cp_commit();
  issue(1, 32); cp_commit();

  for (int it = 0; it < KS; it++) {
    const int s = it % 3;
    cp_wait1();
    __syncthreads();
    if (it + 2 < KS) issue((it + 2) % 3, (it + 2) * 32);
    cp_commit();
    compute(s);
  }

  // epilogue
#pragma unroll
  for (int mt = 0; mt < 4; mt++)
#pragma unroll
    for (int nt = 0; nt < 4; nt++) {
      int row = bm * 128 + wm * 64 + mt * 16 + (lane >> 2);
      int col = colbase + wn * 32 + nt * 8 + (lane & 3) * 2;
      if (dest <= 2) {
        size_t i0 = (size_t)row * N16 + col;
        size_t i1 = i0 + (size_t)8 * N16;
        __half2 v0 = __float22half2_rn(make_float2(ac[mt][nt][0], ac[mt][nt][1]));
        __half2 v1 = __float22half2_rn(make_float2(ac[mt][nt][2], ac[mt][nt][3]));
        *(__half2*)(H16 + i0) = v0;
        *(__half2*)(H16 + i1) = v1;
      } else {
        float* c0 = outC + (size_t)row * 2048 + col;
        *(float2*)c0 = make_float2(ac[mt][nt][0], ac[mt][nt][1]);
        *(float2*)(c0 + 8 * 2048) = make_float2(ac[mt][nt][2], ac[mt][nt][3]);
      }
    }
}

// ========= RoPE + RMSNorm, fp16 in -> fp16 out (merged q+k) =================
#define QW_TOT (MTOK * NH_)
#define KW_TOT (MTOK * NKV_)

__global__ __launch_bounds__(256) void rope_rms_f16(
    const float* __restrict__ qw, const float* __restrict__ kw) {
  int gw = (blockIdx.x * blockDim.x + threadIdx.x) >> 5;
  if (gw >= QW_TOT + KW_TOT) return;
  int lane = threadIdx.x & 31;
  const __half* x;
  const float* w;
  __half* y;
  float osc;
  int lw, nh;
  if (gw < QW_TOT) {
    lw = gw; nh = NH_; x = g_qp16; w = qw; y = g_q16;
    osc = 0.08838834764831845f;  // 1/sqrt(128)
  } else {
    lw = gw - QW_TOT; nh = NKV_; x = g_kp16; w = kw; y = g_k16;
    osc = 1.0f;
  }
  int token = lw / nh;
  int s = token & (Ss_ - 1);
  const __half2* p2 = (const __half2*)(x + (size_t)lw * HD_);

  // lane covers d0 = 2*lane, d1 = 2*lane+1 (paired with d+64)
  float2 x1 = __half22float2(p2[lane]);        // [d0], [d1]
  float2 x2 = __half22float2(p2[lane + 32]);   // [d0+64], [d1+64]

  const float neg_l2theta_over_half = -13.287712379549449f / 64.f;
  int d0 = lane * 2;
  float inv0 = exp2f((float)d0 * neg_l2theta_over_half);
  float inv1 = exp2f((float)(d0 + 1) * neg_l2theta_over_half);
  float c0, s0, c1, s1;
  sincosf((float)s * inv0, &s0, &c0);
  sincosf((float)s * inv1, &s1, &c1);

  float o1x = x1.x * c0 - x2.x * s0;
  float o1y = x1.y * c1 - x2.y * s1;
  float o2x = x2.x * c0 + x1.x * s0;
  float o2y = x2.y * c1 + x1.y * s1;

  float ss = o1x * o1x + o1y * o1y + o2x * o2x + o2y * o2y;
#pragma unroll
  for (int o = 16; o >= 1; o >>= 1) ss += __shfl_xor_sync(0xffffffffu, ss, o);
  float r = rsqrtf(ss * (1.f / 128.f) + 1e-6f) * osc;

  __half2* y2 = (__half2*)(y + (size_t)lw * HD_);
  y2[lane] = __float22half2_rn(
      make_float2(o1x * r * w[d0], o1y * r * w[d0 + 1]));
  y2[lane + 32] = __float22half2_rn(
      make_float2(o2x * r * w[d0 + 64], o2y * r * w[d0 + 65]));
}

// == Flash attention (fp16 1-pass, paired q-tiles, max-free softmax, =========
//    cp.async double-buffered K/V — zero register cost) =======================
#define FPITCH 272
#define FQ 0
#define KVSTG (128 * FPITCH)              // 34816 (K 64 rows + V 64 rows)
#define FKV0 (128 * FPITCH)
#define FKV1 (FKV0 + KVSTG)
#define FA2_SMEM (FKV1 + KVSTG)           // 104448 B -> 2 CTAs/SM
#define KOFF 0
#define VOFF (64 * FPITCH)
#define SM_OFF 4.0f

__global__ __launch_bounds__(256, 2) void flash_attn_f16() {
  extern __shared__ char sm[];
  const uint32_t smb = smem_u32(sm);
  const int bx = blockIdx.x, h = blockIdx.y, b = blockIdx.z;
  const int kvh = h >> 2;
  const int tid = threadIdx.x, wid = tid >> 5, lane = tid & 31;
  const int i4 = lane >> 3, j8 = lane & 7;

  const uint32_t qa_off = (uint32_t)(wid * 16 + (i4 & 1) * 8 + j8) * FPITCH +
                          (uint32_t)((i4 >> 1) * 8) * 2;
  const uint32_t kb_row = (uint32_t)((i4 >> 1) * 8 + j8);
  const uint32_t kb_koff = (uint32_t)((i4 & 1) * 8) * 2;
  const uint32_t v_kv = (uint32_t)((i4 & 1) * 8 + j8);
  const uint32_t v_d = (uint32_t)((i4 >> 1) * 8);
  const int krow = tid >> 2, kqtr = tid & 3;
  const size_t kv_lane_off = (size_t)krow * (NKV_ * HD_) + kvh * HD_ +
                             kqtr * 32;
  const uint32_t kv_smem_off = (uint32_t)(krow * FPITCH + kqtr * 64);

  auto issue_kv = [&](int s, int kvb) {
    const uint32_t st = smb + (s ? FKV1 : FKV0) + kv_smem_off;
    const size_t gb = (size_t)(b * Ss_ + kvb) * (NKV_ * HD_) + kv_lane_off;
#pragma unroll
    for (int q = 0; q < 4; q++) {
      cp16(st + KOFF + q * 16, g_k16 + gb + q * 8);
      cp16(st + VOFF + q * 16, g_v16 + gb + q * 8);
    }
  };

#pragma unroll
  for (int ti = 0; ti < 2; ti++) {
    const int qt = ti ? 15 - bx : bx;
    const int qb = qt * 128;
    const int qwb = qb + wid * 16;
    const int nkv = 2 * qt + 2;

    __syncthreads();

    issue_kv(0, 0);
    cp_commit();

    {
      const int row = tid >> 1, half = tid & 1;
      const size_t gof = (size_t)(b * Ss_ + qb + row) * (NH_ * HD_) + h * HD_ +
                         half * 64;
      const uint4* sq = (const uint4*)(g_q16 + gof);
      char* dq = sm + FQ + row * FPITCH + half * 128;
#pragma unroll
      for (int q = 0; q < 8; q++) *(uint4*)(dq + q * 16) = sq[q];
    }

    float oa[16][4];
#pragma unroll
    for (int nt = 0; nt < 16; nt++)
#pragma unroll
      for (int q = 0; q < 4; q++) oa[nt][q] = 0.f;
    float l0 = 0.f, l1 = 0.f;

    for (int kvi = 0; kvi < nkv; kvi++) {
      const int kvb = kvi * 64;
      const uint32_t buf = smb + ((kvi & 1) ? FKV1 : FKV0);

      if (kvi) __syncthreads();
      if (kvi + 1 < nkv) {
        issue_kv((kvi + 1) & 1, kvb + 64);
        cp_commit();
        cp_wait1();
      } else {
        cp_wait0();
      }
      __syncthreads();

      if (kvb > qwb + 15) continue;

      float s4[8][4];
#pragma unroll
      for (int j = 0; j < 8; j++)
#pragma unroll
        for (int q = 0; q < 4; q++) s4[j][q] = 0.f;

#pragma unroll
      for (int kt = 0; kt < 8; kt++) {
        uint32_t aQ[4];
        ldsm4(smb + FQ + qa_off + kt * 32, aQ);
#pragma unroll
        for (int p = 0; p < 4; p++) {
          uint32_t rK[4];
          uint32_t ka = (uint32_t)(p * 16) * FPITCH + kb_row * FPITCH +
                        kb_koff + (uint32_t)(kt * 32);
          ldsm4(buf + KOFF + ka, rK);
          mmaf16(s4[2 * p],     aQ, rK[0], rK[1]);
          mmaf16(s4[2 * p + 1], aQ, rK[2], rK[3]);
        }
      }

      if (kvb + 63 > qwb) {
        const int qr0 = qwb + (lane >> 2), qr1 = qr0 + 8;
        const int kc0 = kvb + (lane & 3) * 2;
#pragma unroll
        for (int j = 0; j < 8; j++) {
          int kv0 = kc0 + j * 8, kv1 = kv0 + 1;
          if (kv0 > qr0) s4[j][0] = -1e30f;
          if (kv1 > qr0) s4[j][1] = -1e30f;
          if (kv0 > qr1) s4[j][2] = -1e30f;
          if (kv1 > qr1) s4[j][3] = -1e30f;
        }
      }

      float sum0 = 0.f, sum1 = 0.f;
#pragma unroll
      for (int j = 0; j < 8; j++) {
        s4[j][0] = __expf(s4[j][0] - SM_OFF);
        s4[j][1] = __expf(s4[j][1] - SM_OFF);
        s4[j][2] = __expf(s4[j][2] - SM_OFF);
        s4[j][3] = __expf(s4[j][3] - SM_OFF);
        sum0 += s4[j][0] + s4[j][1];
        sum1 += s4[j][2] + s4[j][3];
      }
      sum0 += __shfl_xor_sync(0xffffffffu, sum0, 1);
      sum0 += __shfl_xor_sync(0xffffffffu, sum0, 2);
      sum1 += __shfl_xor_sync(0xffffffffu, sum1, 1);
      sum1 += __shfl_xor_sync(0xffffffffu, sum1, 2);
      l0 += sum0;
      l1 += sum1;

#pragma unroll
      for (int kt = 0; kt < 4; kt++) {
        uint32_t aP[4];
        {
          __half2 p0 = __float22half2_rn(
              make_float2(s4[2 * kt][0], s4[2 * kt][1]));
          __half2 p1 = __float22half2_rn(
              make_float2(s4[2 * kt][2], s4[2 * kt][3]));
          __half2 p2 = __float22half2_rn(
              make_float2(s4[2 * kt + 1][0], s4[2 * kt + 1][1]));
          __half2 p3 = __float22half2_rn(
              make_float2(s4[2 * kt + 1][2], s4[2 * kt + 1][3]));
          aP[0] = *reinterpret_cast<uint32_t*>(&p0);
          aP[1] = *reinterpret_cast<uint32_t*>(&p1);
          aP[2] = *reinterpret_cast<uint32_t*>(&p2);
          aP[3] = *reinterpret_cast<uint32_t*>(&p3);
        }
#pragma unroll
        for (int p = 0; p < 8; p++) {
          uint32_t rV[4];
          uint32_t va = (uint32_t)(kt * 16 + v_kv) * FPITCH +
                        (uint32_t)(p * 16 + v_d) * 2;
          ldsm4t(buf + VOFF + va, rV);
          mmaf16(oa[2 * p],     aP, rV[0], rV[1]);
          mmaf16(oa[2 * p + 1], aP, rV[2], rV[3]);
        }
      }
    }

    const float inv0 = 1.0f / l0, inv1 = 1.0f / l1;
    const int r0 = qwb + (lane >> 2);
#pragma unroll
    for (int nt = 0; nt < 16; nt++) {
      int col = h * HD_ + nt * 8 + (lane & 3) * 2;
      size_t idx0 = (size_t)(b * Ss_ + r0) * (NH_ * HD_) + col;
      size_t idx1 = (size_t)(b * Ss_ + r0 + 8) * (NH_ * HD_) + col;
      __half2 o0 = __float22half2_rn(make_float2(oa[nt][0] * inv0,
                                                 oa[nt][1] * inv0));
      __half2 o1 = __float22half2_rn(make_float2(oa[nt][2] * inv1,
                                                 oa[nt][3] * inv1));
      *(__half2*)(g_a16 + idx0) = o0;
      *(__half2*)(g_a16 + idx1) = o1;
    }
  }
}

// ============================ launch ========================================
extern "C" void kernel_launch(void* const* d_in, const int* in_sizes, int n_in,
                              void* d_out, int out_size) {
  const float* hs = (const float*)d_in[0];
  const float* wq = (const float*)d_in[1];
  const float* wk = (const float*)d_in[2];
  const float* wv = (const float*)d_in[3];
  const float* wo = (const float*)d_in[4];
  const float* qw = (const float*)d_in[5];
  const float* kw = (const float*)d_in[6];
  float* out = (float*)d_out;

  cudaFuncSetAttribute(gemm_f16, cudaFuncAttributeMaxDynamicSharedMemorySize,
                       GSM);
  cudaFuncSetAttribute(flash_attn_f16,
                       cudaFuncAttributeMaxDynamicSharedMemorySize, FA2_SMEM);

  // merged prep: fp16 rounding of hs + all weights
  round_all<<<(N4_TOT + 255) / 256, 256>>>(hs, wq, wk, wv, wo);

  // Fused Q+K+V projections (fp16 1-pass, fp16 outputs)
  gemm_f16<<<dim3(12, MTOK / 128), 512, GSM>>>(0, nullptr);

  // RoPE + RMSNorm (fp16 in/out; q pre-scaled by 1/sqrt(HD))
  rope_rms_f16<<<((QW_TOT + KW_TOT) * 32 + 255) / 256, 256>>>(qw, kw);

  // Flash attention, paired q-tiles, cp.async double-buffered K/V
  flash_attn_f16<<<dim3(8, NH_, Bb_), 256, FA2_SMEM>>>();

  // Output projection (fp16 1-pass) -> d_out
  gemm_f16<<<dim3(Hh_ / 256, MTOK / 128), 512, GSM>>>(1, out);
}

// round 15
// speedup vs baseline: 1.1078x; 1.1078x over previous
#include <cuda_runtime.h>
#include <cuda_fp16.h>
#include <math.h>
#include <stdint.h>

#define Bb_ 2
#define Ss_ 2048
#define Hh_ 2048
#define NH_ 16
#define NKV_ 4
#define HD_ 128
#define MTOK (Bb_ * Ss_)   // 4096 tokens

// Scratch (allocation-free rule: __device__ globals)
__device__ float g_q[(size_t)MTOK * NH_ * HD_];    // fp32 pre-rope Q
__device__ float g_k[(size_t)MTOK * NKV_ * HD_];   // fp32 pre-rope K
// fp16 GEMM operands (single-rounded)
__device__ __half g_hs16[(size_t)MTOK * Hh_];
__device__ __half g_wq16[(size_t)NH_ * HD_ * Hh_];
__device__ __half g_wk16[(size_t)NKV_ * HD_ * Hh_];
__device__ __half g_wv16[(size_t)NKV_ * HD_ * Hh_];
// attention inputs (fp16, single)
__device__ __half g_q16[(size_t)MTOK * NH_ * HD_];
__device__ __half g_k16[(size_t)MTOK * NKV_ * HD_];
__device__ __half g_v16[(size_t)MTOK * NKV_ * HD_];
// O-proj operands (fp16 1-pass)
__device__ __half g_wo16[(size_t)Hh_ * NH_ * HD_];
__device__ __half g_a16[(size_t)MTOK * NH_ * HD_];

// ============================ helpers =======================================
__device__ __forceinline__ uint32_t smem_u32(const void* p) {
  uint32_t a;
  asm("{ .reg .u64 t; cvta.to.shared.u64 t, %1; cvt.u32.u64 %0, t; }"
      : "=r"(a) : "l"(p));
  return a;
}
__device__ __forceinline__ void cp16(uint32_t dst, const void* src) {
  asm volatile("cp.async.cg.shared.global [%0], [%1], 16;"
               :: "r"(dst), "l"(src));
}
__device__ __forceinline__ void cp_commit() {
  asm volatile("cp.async.commit_group;" ::: "memory");
}
__device__ __forceinline__ void cp_wait1() {
  asm volatile("cp.async.wait_group 1;" ::: "memory");
}
__device__ __forceinline__ void cp_wait0() {
  asm volatile("cp.async.wait_group 0;" ::: "memory");
}
__device__ __forceinline__ void ldsm4(uint32_t addr, uint32_t r[4]) {
  asm volatile("ldmatrix.sync.aligned.m8n8.x4.shared.b16 {%0,%1,%2,%3}, [%4];"
               : "=r"(r[0]), "=r"(r[1]), "=r"(r[2]), "=r"(r[3]) : "r"(addr));
}
__device__ __forceinline__ void ldsm4t(uint32_t addr, uint32_t r[4]) {
  asm volatile(
      "ldmatrix.sync.aligned.m8n8.x4.trans.shared.b16 {%0,%1,%2,%3}, [%4];"
      : "=r"(r[0]), "=r"(r[1]), "=r"(r[2]), "=r"(r[3]) : "r"(addr));
}
__device__ __forceinline__ void mmaf16(float c[4], const uint32_t a[4],
                                       uint32_t b0, uint32_t b1) {
  asm volatile(
      "mma.sync.aligned.m16n8k16.row.col.f32.f16.f16.f32 "
      "{%0,%1,%2,%3}, {%4,%5,%6,%7}, {%8,%9}, {%0,%1,%2,%3};"
      : "+f"(c[0]), "+f"(c[1]), "+f"(c[2]), "+f"(c[3])
      : "r"(a[0]), "r"(a[1]), "r"(a[2]), "r"(a[3]), "r"(b0), "r"(b1));
}

// ============================ prep kernel (merged) ==========================
#define N4_HS (MTOK * Hh_ / 4)            // 2M
#define N4_WQ (NH_ * HD_ * Hh_ / 4)       // 1M
#define N4_WKV (NKV_ * HD_ * Hh_ / 4)     // 256K
#define N4_TOT (N4_HS + N4_WQ + 2 * N4_WKV + N4_WQ)

__global__ __launch_bounds__(256) void round_all(
    const float* __restrict__ hs, const float* __restrict__ wq,
    const float* __restrict__ wk, const float* __restrict__ wv,
    const float* __restrict__ wo) {
  int i = blockIdx.x * blockDim.x + threadIdx.x;
  if (i >= N4_TOT) return;
  const float* src;
  __half* dst;
  int off;
  if (i < N4_HS) {
    src = hs; dst = g_hs16; off = i;
  } else if (i < N4_HS + N4_WQ) {
    src = wq; dst = g_wq16; off = i - N4_HS;
  } else if (i < N4_HS + N4_WQ + N4_WKV) {
    src = wk; dst = g_wk16; off = i - N4_HS - N4_WQ;
  } else if (i < N4_HS + N4_WQ + 2 * N4_WKV) {
    src = wv; dst = g_wv16; off = i - N4_HS - N4_WQ - N4_WKV;
  } else {
    src = wo; dst = g_wo16; off = i - N4_HS - N4_WQ - 2 * N4_WKV;
  }
  float4 v = ((const float4*)src)[off];
  __half2 a = __float22half2_rn(make_float2(v.x, v.y));
  __half2 b = __float22half2_rn(make_float2(v.z, v.w));
  ((uint2*)dst)[off] = make_uint2(*reinterpret_cast<uint32_t*>(&a),
                                  *reinterpret_cast<uint32_t*>(&b));
}

// ====== fp16 1-pass GEMM, BK=64, cp.async 3-stage, 512 threads ==============
// CTA tile 128x256, BK=64, 16 warps (2m x 8n, warp tile 64x32).
// smem pitch 144 B per 64-fp16 row (16 mod 128 -> conflict-free ldmatrix).
#define GP 144
#define A_MAT (128 * GP)            // 18432 B
#define B_MAT (256 * GP)            // 36864 B
#define STG (A_MAT + B_MAT)         // 55296 B
#define GSM (3 * STG)               // 165888 B
#define KDIM 2048

// mode 0: fused QKV (bn<8 Q fp32, 8..9 K fp32, 10..11 V fp16)
// mode 1: O proj (A = g_a16, B = g_wo16, C = outC fp32)
__global__ __launch_bounds__(512, 1) void gemm_f16(int mode, float* outC) {
  extern __shared__ char sm[];
  const uint32_t smb = smem_u32(sm);
  const int tid = threadIdx.x, wid = tid >> 5, lane = tid & 31;
  const int wm = wid & 1, wn = wid >> 1;
  const int bn = blockIdx.x, bm = blockIdx.y;
  const int i4 = lane >> 3, j8 = lane & 7;

  const __half *Ab, *Bb;
  int colbase, dest;  // 0=Q fp32, 1=K fp32, 2=V fp16, 3=out fp32
  if (mode == 0) {
    Ab = g_hs16 + (size_t)(bm * 128) * KDIM;
    if (bn < 8) {
      Bb = g_wq16 + (size_t)(bn * 256) * KDIM;
      colbase = bn * 256; dest = 0;
    } else if (bn < 10) {
      Bb = g_wk16 + (size_t)((bn - 8) * 256) * KDIM;
      colbase = (bn - 8) * 256; dest = 1;
    } else {
      Bb = g_wv16 + (size_t)((bn - 10) * 256) * KDIM;
      colbase = (bn - 10) * 256; dest = 2;
    }
  } else {
    Ab = g_a16 + (size_t)(bm * 128) * KDIM;
    Bb = g_wo16 + (size_t)(bn * 256) * KDIM;
    colbase = bn * 256; dest = 3;
  }

  float ac[4][4][4];
#pragma unroll
  for (int mt = 0; mt < 4; mt++)
#pragma unroll
    for (int nt = 0; nt < 4; nt++)
#pragma unroll
      for (int q = 0; q < 4; q++) ac[mt][nt][q] = 0.f;

  // BK=64: A = 128 rows x 8 chunks(16B) = 1024 lines; B = 256 x 8 = 2048
  auto issue = [&](int s, int k0) {
    const uint32_t st = smb + s * STG;
#pragma unroll
    for (int i = 0; i < 2; i++) {
      int e = i * 512 + tid;
      int r = e >> 3, c = e & 7;
      size_t go = (size_t)r * KDIM + k0 + c * 8;
      uint32_t so = (uint32_t)(r * GP + c * 16);
      cp16(st + so, Ab + go);
    }
#pragma unroll
    for (int i = 0; i < 4; i++) {
      int e = i * 512 + tid;
      int r = e >> 3, c = e & 7;
      size_t go = (size_t)r * KDIM + k0 + c * 8;
      uint32_t so = (uint32_t)(r * GP + c * 16);
      cp16(st + A_MAT + so, Bb + go);
    }
  };

  auto compute = [&](int s) {
    const uint32_t base = smb + s * STG;
#pragma unroll
    for (int ks = 0; ks < 4; ks++) {
      uint32_t af[4][4];
#pragma unroll
      for (int mt = 0; mt < 4; mt++) {
        uint32_t addr = base +
                        (uint32_t)(wm * 64 + mt * 16 + (i4 & 1) * 8 + j8) * GP +
                        (uint32_t)((i4 >> 1) * 8 + ks * 16) * 2;
        ldsm4(addr, af[mt]);
      }
      uint32_t bf[4][2];
#pragma unroll
      for (int p = 0; p < 2; p++) {
        uint32_t r[4];
        uint32_t addr = base + A_MAT +
                        (uint32_t)(wn * 32 + p * 16 + (i4 >> 1) * 8 + j8) * GP +
                        (uint32_t)((i4 & 1) * 8 + ks * 16) * 2;
        ldsm4(addr, r);
        bf[2 * p][0] = r[0]; bf[2 * p][1] = r[1];
        bf[2 * p + 1][0] = r[2]; bf[2 * p + 1][1] = r[3];
      }
#pragma unroll
      for (int mt = 0; mt < 4; mt++)
#pragma unroll
        for (int nt = 0; nt < 4; nt++)
          mmaf16(ac[mt][nt], af[mt], bf[nt][0], bf[nt][1]);
    }
  };

  const int KS = KDIM >> 6;  // 32
  issue(0, 0); cp_commit();
  issue(1, 64); cp_commit();

  for (int it = 0; it < KS; it++) {
    const int s = it % 3;
    cp_wait1();
    __syncthreads();
    if (it + 2 < KS) issue((it + 2) % 3, (it + 2) * 64);
    cp_commit();
    compute(s);
  }

  // epilogue
#pragma unroll
  for (int mt = 0; mt < 4; mt++)
#pragma unroll
    for (int nt = 0; nt < 4; nt++) {
      int row = bm * 128 + wm * 64 + mt * 16 + (lane >> 2);
      int col = colbase + wn * 32 + nt * 8 + (lane & 3) * 2;
      if (dest == 0) {
        float* c0 = g_q + (size_t)row * 2048 + col;
        *(float2*)c0 = make_float2(ac[mt][nt][0], ac[mt][nt][1]);
        *(float2*)(c0 + 8 * 2048) = make_float2(ac[mt][nt][2], ac[mt][nt][3]);
      } else if (dest == 1) {
        float* c0 = g_k + (size_t)row * 512 + col;
        *(float2*)c0 = make_float2(ac[mt][nt][0], ac[mt][nt][1]);
        *(float2*)(c0 + 8 * 512) = make_float2(ac[mt][nt][2], ac[mt][nt][3]);
      } else if (dest == 2) {
        size_t i0 = (size_t)row * 512 + col;
        size_t i1 = i0 + 8 * 512;
        __half2 v0 = __float22half2_rn(make_float2(ac[mt][nt][0], ac[mt][nt][1]));
        __half2 v1 = __float22half2_rn(make_float2(ac[mt][nt][2], ac[mt][nt][3]));
        *(__half2*)(g_v16 + i0) = v0;
        *(__half2*)(g_v16 + i1) = v1;
      } else {
        float* c0 = outC + (size_t)row * 2048 + col;
        *(float2*)c0 = make_float2(ac[mt][nt][0], ac[mt][nt][1]);
        *(float2*)(c0 + 8 * 2048) = make_float2(ac[mt][nt][2], ac[mt][nt][3]);
      }
    }
}

// =============== RoPE + RMSNorm -> single fp16 (merged q+k) =================
#define QW_TOT (MTOK * NH_)
#define KW_TOT (MTOK * NKV_)

__global__ __launch_bounds__(256) void rope_rms_f16(
    const float* __restrict__ qw, const float* __restrict__ kw) {
  int gw = (blockIdx.x * blockDim.x + threadIdx.x) >> 5;
  if (gw >= QW_TOT + KW_TOT) return;
  int lane = threadIdx.x & 31;
  const float* x;
  const float* w;
  __half* y;
  float osc;
  int lw, nh;
  if (gw < QW_TOT) {
    lw = gw; nh = NH_; x = g_q; w = qw; y = g_q16;
    osc = 0.08838834764831845f;  // 1/sqrt(128)
  } else {
    lw = gw - QW_TOT; nh = NKV_; x = g_k; w = kw; y = g_k16;
    osc = 1.0f;
  }
  int token = lw / nh;
  int s = token & (Ss_ - 1);
  const float* p = x + (size_t)lw * HD_;

  const float neg_l2theta_over_half = -13.287712379549449f / 64.f;
  float vals[4];
  float ss = 0.f;
#pragma unroll
  for (int hh = 0; hh < 2; hh++) {
    int d = lane + hh * 32;
    float x1 = p[d];
    float x2 = p[d + 64];
    float invf = exp2f((float)d * neg_l2theta_over_half);
    float ang = (float)s * invf;
    float c, sn;
    sincosf(ang, &sn, &c);
    float o1 = x1 * c - x2 * sn;
    float o2 = x2 * c + x1 * sn;
    vals[hh * 2] = o1;
    vals[hh * 2 + 1] = o2;
    ss += o1 * o1 + o2 * o2;
  }
#pragma unroll
  for (int o = 16; o >= 1; o >>= 1) ss += __shfl_xor_sync(0xffffffffu, ss, o);
  float r = rsqrtf(ss * (1.f / 128.f) + 1e-6f) * osc;
#pragma unroll
  for (int hh = 0; hh < 2; hh++) {
    int d = lane + hh * 32;
    size_t base = (size_t)lw * HD_;
    y[base + d] = __float2half_rn(vals[hh * 2] * r * w[d]);
    y[base + d + 64] = __float2half_rn(vals[hh * 2 + 1] * r * w[d + 64]);
  }
}

// == Flash attention (fp16 1-pass, paired q-tiles, max-free softmax, =========
//    cp.async double-buffered K/V) ===========================================
#define FPITCH 272
#define FQ 0
#define KVSTG (128 * FPITCH)              // 34816 (K 64 rows + V 64 rows)
#define FKV0 (128 * FPITCH)
#define FKV1 (FKV0 + KVSTG)
#define FA2_SMEM (FKV1 + KVSTG)           // 104448 B -> 2 CTAs/SM
#define KOFF 0
#define VOFF (64 * FPITCH)
#define SM_OFF 4.0f

__global__ __launch_bounds__(256, 2) void flash_attn_f16() {
  extern __shared__ char sm[];
  const uint32_t smb = smem_u32(sm);
  const int bx = blockIdx.x, h = blockIdx.y, b = blockIdx.z;
  const int kvh = h >> 2;
  const int tid = threadIdx.x, wid = tid >> 5, lane = tid & 31;
  const int i4 = lane >> 3, j8 = lane & 7;

  const uint32_t qa_off = (uint32_t)(wid * 16 + (i4 & 1) * 8 + j8) * FPITCH +
                          (uint32_t)((i4 >> 1) * 8) * 2;
  const uint32_t kb_row = (uint32_t)((i4 >> 1) * 8 + j8);
  const uint32_t kb_koff = (uint32_t)((i4 & 1) * 8) * 2;
  const uint32_t v_kv = (uint32_t)((i4 & 1) * 8 + j8);
  const uint32_t v_d = (uint32_t)((i4 >> 1) * 8);
  const int krow = tid >> 2, kqtr = tid & 3;
  const size_t kv_lane_off = (size_t)krow * (NKV_ * HD_) + kvh * HD_ +
                             kqtr * 32;
  const uint32_t kv_smem_off = (uint32_t)(krow * FPITCH + kqtr * 64);

  auto issue_kv = [&](int s, int kvb) {
    const uint32_t st = smb + (s ? FKV1 : FKV0) + kv_smem_off;
    const size_t gb = (size_t)(b * Ss_ + kvb) * (NKV_ * HD_) + kv_lane_off;
#pragma unroll
    for (int q = 0; q < 4; q++) {
      cp16(st + KOFF + q * 16, g_k16 + gb + q * 8);
      cp16(st + VOFF + q * 16, g_v16 + gb + q * 8);
    }
  };

#pragma unroll
  for (int ti = 0; ti < 2; ti++) {
    const int qt = ti ? 15 - bx : bx;   // paired tiles: uniform 34 chunks/CTA
    const int qb = qt * 128;
    const int qwb = qb + wid * 16;
    const int nkv = 2 * qt + 2;

    __syncthreads();

    issue_kv(0, 0);
    cp_commit();

    {
      const int row = tid >> 1, half = tid & 1;
      const size_t gof = (size_t)(b * Ss_ + qb + row) * (NH_ * HD_) + h * HD_ +
                         half * 64;
      const uint4* sq = (const uint4*)(g_q16 + gof);
      char* dq = sm + FQ + row * FPITCH + half * 128;
#pragma unroll
      for (int q = 0; q < 8; q++) *(uint4*)(dq + q * 16) = sq[q];
    }

    float oa[16][4];
#pragma unroll
    for (int nt = 0; nt < 16; nt++)
#pragma unroll
      for (int q = 0; q < 4; q++) oa[nt][q] = 0.f;
    float l0 = 0.f, l1 = 0.f;

    for (int kvi = 0; kvi < nkv; kvi++) {
      const int kvb = kvi * 64;
      const uint32_t buf = smb + ((kvi & 1) ? FKV1 : FKV0);

      if (kvi) __syncthreads();
      if (kvi + 1 < nkv) {
        issue_kv((kvi + 1) & 1, kvb + 64);
        cp_commit();
        cp_wait1();
      } else {
        cp_wait0();
      }
      __syncthreads();

      if (kvb > qwb + 15) continue;

      float s4[8][4];
#pragma unroll
      for (int j = 0; j < 8; j++)
#pragma unroll
        for (int q = 0; q < 4; q++) s4[j][q] = 0.f;

#pragma unroll
      for (int kt = 0; kt < 8; kt++) {
        uint32_t aQ[4];
        ldsm4(smb + FQ + qa_off + kt * 32, aQ);
#pragma unroll
        for (int p = 0; p < 4; p++) {
          uint32_t rK[4];
          uint32_t ka = (uint32_t)(p * 16) * FPITCH + kb_row * FPITCH +
                        kb_koff + (uint32_t)(kt * 32);
          ldsm4(buf + KOFF + ka, rK);
          mmaf16(s4[2 * p],     aQ, rK[0], rK[1]);
          mmaf16(s4[2 * p + 1], aQ, rK[2], rK[3]);
        }
      }

      if (kvb + 63 > qwb) {
        const int qr0 = qwb + (lane >> 2), qr1 = qr0 + 8;
        const int kc0 = kvb + (lane & 3) * 2;
#pragma unroll
        for (int j = 0; j < 8; j++) {
          int kv0 = kc0 + j * 8, kv1 = kv0 + 1;
          if (kv0 > qr0) s4[j][0] = -1e30f;
          if (kv1 > qr0) s4[j][1] = -1e30f;
          if (kv0 > qr1) s4[j][2] = -1e30f;
          if (kv1 > qr1) s4[j][3] = -1e30f;
        }
      }

      float sum0 = 0.f, sum1 = 0.f;
#pragma unroll
      for (int j = 0; j < 8; j++) {
        s4[j][0] = __expf(s4[j][0] - SM_OFF);
        s4[j][1] = __expf(s4[j][1] - SM_OFF);
        s4[j][2] = __expf(s4[j][2] - SM_OFF);
        s4[j][3] = __expf(s4[j][3] - SM_OFF);
        sum0 += s4[j][0] + s4[j][1];
        sum1 += s4[j][2] + s4[j][3];
      }
      sum0 += __shfl_xor_sync(0xffffffffu, sum0, 1);
      sum0 += __shfl_xor_sync(0xffffffffu, sum0, 2);
      sum1 += __shfl_xor_sync(0xffffffffu, sum1, 1);
      sum1 += __shfl_xor_sync(0xffffffffu, sum1, 2);
      l0 += sum0;
      l1 += sum1;

#pragma unroll
      for (int kt = 0; kt < 4; kt++) {
        uint32_t aP[4];
        {
          __half2 p0 = __float22half2_rn(
              make_float2(s4[2 * kt][0], s4[2 * kt][1]));
          __half2 p1 = __float22half2_rn(
              make_float2(s4[2 * kt][2], s4[2 * kt][3]));
          __half2 p2 = __float22half2_rn(
              make_float2(s4[2 * kt + 1][0], s4[2 * kt + 1][1]));
          __half2 p3 = __float22half2_rn(
              make_float2(s4[2 * kt + 1][2], s4[2 * kt + 1][3]));
          aP[0] = *reinterpret_cast<uint32_t*>(&p0);
          aP[1] = *reinterpret_cast<uint32_t*>(&p1);
          aP[2] = *reinterpret_cast<uint32_t*>(&p2);
          aP[3] = *reinterpret_cast<uint32_t*>(&p3);
        }
#pragma unroll
        for (int p = 0; p < 8; p++) {
          uint32_t rV[4];
          uint32_t va = (uint32_t)(kt * 16 + v_kv) * FPITCH +
                        (uint32_t)(p * 16 + v_d) * 2;
          ldsm4t(buf + VOFF + va, rV);
          mmaf16(oa[2 * p],     aP, rV[0], rV[1]);
          mmaf16(oa[2 * p + 1], aP, rV[2], rV[3]);
        }
      }
    }

    const float inv0 = 1.0f / l0, inv1 = 1.0f / l1;
    const int r0 = qwb + (lane >> 2);
#pragma unroll
    for (int nt = 0; nt < 16; nt++) {
      int col = h * HD_ + nt * 8 + (lane & 3) * 2;
      size_t idx0 = (size_t)(b * Ss_ + r0) * (NH_ * HD_) + col;
      size_t idx1 = (size_t)(b * Ss_ + r0 + 8) * (NH_ * HD_) + col;
      __half2 o0 = __float22half2_rn(make_float2(oa[nt][0] * inv0,
                                                 oa[nt][1] * inv0));
      __half2 o1 = __float22half2_rn(make_float2(oa[nt][2] * inv1,
                                                 oa[nt][3] * inv1));
      *(__half2*)(g_a16 + idx0) = o0;
      *(__half2*)(g_a16 + idx1) = o1;
    }
  }
}

// ============================ launch ========================================
extern "C" void kernel_launch(void* const* d_in, const int* in_sizes, int n_in,
                              void* d_out, int out_size) {
  const float* hs = (const float*)d_in[0];
  const float* wq = (const float*)d_in[1];
  const float* wk = (const float*)d_in[2];
  const float* wv = (const float*)d_in[3];
  const float* wo = (const float*)d_in[4];
  const float* qw = (const float*)d_in[5];
  const float* kw = (const float*)d_in[6];
  float* out = (float*)d_out;

  cudaFuncSetAttribute(gemm_f16, cudaFuncAttributeMaxDynamicSharedMemorySize,
                       GSM);
  cudaFuncSetAttribute(flash_attn_f16,
                       cudaFuncAttributeMaxDynamicSharedMemorySize, FA2_SMEM);

  // merged prep: fp16 rounding of hs + all weights
  round_all<<<(N4_TOT + 255) / 256, 256>>>(hs, wq, wk, wv, wo);

  // Fused Q+K+V projections (fp16 1-pass, BK=64)
  gemm_f16<<<dim3(12, MTOK / 128), 512, GSM>>>(0, nullptr);

  // RoPE + RMSNorm (merged q+k; q pre-scaled by 1/sqrt(HD))
  rope_rms_f16<<<((QW_TOT + KW_TOT) * 32 + 255) / 256, 256>>>(qw, kw);

  // Flash attention, paired q-tiles, cp.async double-buffered K/V
  flash_attn_f16<<<dim3(8, NH_, Bb_), 256, FA2_SMEM>>>();

  // Output projection (fp16 1-pass, BK=64) -> d_out
  gemm_f16<<<dim3(Hh_ / 256, MTOK / 128), 512, GSM>>>(1, out);
}

// round 16
// speedup vs baseline: 1.1549x; 1.0425x over previous
#include <cuda_runtime.h>
#include <cuda_fp16.h>
#include <math.h>
#include <stdint.h>

#define Bb_ 2
#define Ss_ 2048
#define Hh_ 2048
#define NH_ 16
#define NKV_ 4
#define HD_ 128
#define MTOK (Bb_ * Ss_)   // 4096 tokens

// Scratch (allocation-free rule: __device__ globals)
__device__ float g_q[(size_t)MTOK * NH_ * HD_];    // fp32 pre-rope Q
__device__ float g_k[(size_t)MTOK * NKV_ * HD_];   // fp32 pre-rope K
// fp16 GEMM operands (single-rounded)
__device__ __half g_hs16[(size_t)MTOK * Hh_];
__device__ __half g_wq16[(size_t)NH_ * HD_ * Hh_];
__device__ __half g_wk16[(size_t)NKV_ * HD_ * Hh_];
__device__ __half g_wv16[(size_t)NKV_ * HD_ * Hh_];
// attention inputs (fp16, single)
__device__ __half g_q16[(size_t)MTOK * NH_ * HD_];
__device__ __half g_k16[(size_t)MTOK * NKV_ * HD_];
__device__ __half g_v16[(size_t)MTOK * NKV_ * HD_];
// O-proj operands (fp16 1-pass)
__device__ __half g_wo16[(size_t)Hh_ * NH_ * HD_];
__device__ __half g_a16[(size_t)MTOK * NH_ * HD_];

// ============================ helpers =======================================
__device__ __forceinline__ uint32_t smem_u32(const void* p) {
  uint32_t a;
  asm("{ .reg .u64 t; cvta.to.shared.u64 t, %1; cvt.u32.u64 %0, t; }"
      : "=r"(a) : "l"(p));
  return a;
}
__device__ __forceinline__ void cp16(uint32_t dst, const void* src) {
  asm volatile("cp.async.cg.shared.global [%0], [%1], 16;"
               :: "r"(dst), "l"(src));
}
__device__ __forceinline__ void cp_commit() {
  asm volatile("cp.async.commit_group;" ::: "memory");
}
__device__ __forceinline__ void cp_wait1() {
  asm volatile("cp.async.wait_group 1;" ::: "memory");
}
__device__ __forceinline__ void cp_wait0() {
  asm volatile("cp.async.wait_group 0;" ::: "memory");
}
__device__ __forceinline__ void ldsm4(uint32_t addr, uint32_t r[4]) {
  asm volatile("ldmatrix.sync.aligned.m8n8.x4.shared.b16 {%0,%1,%2,%3}, [%4];"
               : "=r"(r[0]), "=r"(r[1]), "=r"(r[2]), "=r"(r[3]) : "r"(addr));
}
__device__ __forceinline__ void ldsm4t(uint32_t addr, uint32_t r[4]) {
  asm volatile(
      "ldmatrix.sync.aligned.m8n8.x4.trans.shared.b16 {%0,%1,%2,%3}, [%4];"
      : "=r"(r[0]), "=r"(r[1]), "=r"(r[2]), "=r"(r[3]) : "r"(addr));
}
__device__ __forceinline__ void mmaf16(float c[4], const uint32_t a[4],
                                       uint32_t b0, uint32_t b1) {
  asm volatile(
      "mma.sync.aligned.m16n8k16.row.col.f32.f16.f16.f32 "
      "{%0,%1,%2,%3}, {%4,%5,%6,%7}, {%8,%9}, {%0,%1,%2,%3};"
      : "+f"(c[0]), "+f"(c[1]), "+f"(c[2]), "+f"(c[3])
      : "r"(a[0]), "r"(a[1]), "r"(a[2]), "r"(a[3]), "r"(b0), "r"(b1));
}

// ============================ prep kernel (merged) ==========================
#define N4_HS (MTOK * Hh_ / 4)            // 2M
#define N4_WQ (NH_ * HD_ * Hh_ / 4)       // 1M
#define N4_WKV (NKV_ * HD_ * Hh_ / 4)     // 256K
#define N4_TOT (N4_HS + N4_WQ + 2 * N4_WKV + N4_WQ)

__global__ __launch_bounds__(256) void round_all(
    const float* __restrict__ hs, const float* __restrict__ wq,
    const float* __restrict__ wk, const float* __restrict__ wv,
    const float* __restrict__ wo) {
  int i = blockIdx.x * blockDim.x + threadIdx.x;
  if (i >= N4_TOT) return;
  const float* src;
  __half* dst;
  int off;
  if (i < N4_HS) {
    src = hs; dst = g_hs16; off = i;
  } else if (i < N4_HS + N4_WQ) {
    src = wq; dst = g_wq16; off = i - N4_HS;
  } else if (i < N4_HS + N4_WQ + N4_WKV) {
    src = wk; dst = g_wk16; off = i - N4_HS - N4_WQ;
  } else if (i < N4_HS + N4_WQ + 2 * N4_WKV) {
    src = wv; dst = g_wv16; off = i - N4_HS - N4_WQ - N4_WKV;
  } else {
    src = wo; dst = g_wo16; off = i - N4_HS - N4_WQ - 2 * N4_WKV;
  }
  float4 v = ((const float4*)src)[off];
  __half2 a = __float22half2_rn(make_float2(v.x, v.y));
  __half2 b = __float22half2_rn(make_float2(v.z, v.w));
  ((uint2*)dst)[off] = make_uint2(*reinterpret_cast<uint32_t*>(&a),
                                  *reinterpret_cast<uint32_t*>(&b));
}

// ====== fp16 1-pass GEMM, BK=64, cp.async 3-stage, 512 threads ==============
#define GP 144
#define A_MAT (128 * GP)            // 18432 B
#define B_MAT (256 * GP)            // 36864 B
#define STG (A_MAT + B_MAT)         // 55296 B
#define GSM (3 * STG)               // 165888 B
#define KDIM 2048

// mode 0: fused QKV (bn<8 Q fp32, 8..9 K fp32, 10..11 V fp16)
// mode 1: O proj (A = g_a16, B = g_wo16, C = outC fp32)
__global__ __launch_bounds__(512, 1) void gemm_f16(int mode, float* outC) {
  extern __shared__ char sm[];
  const uint32_t smb = smem_u32(sm);
  const int tid = threadIdx.x, wid = tid >> 5, lane = tid & 31;
  const int wm = wid & 1, wn = wid >> 1;
  const int bn = blockIdx.x, bm = blockIdx.y;
  const int i4 = lane >> 3, j8 = lane & 7;

  const __half *Ab, *Bb;
  int colbase, dest;  // 0=Q fp32, 1=K fp32, 2=V fp16, 3=out fp32
  if (mode == 0) {
    Ab = g_hs16 + (size_t)(bm * 128) * KDIM;
    if (bn < 8) {
      Bb = g_wq16 + (size_t)(bn * 256) * KDIM;
      colbase = bn * 256; dest = 0;
    } else if (bn < 10) {
      Bb = g_wk16 + (size_t)((bn - 8) * 256) * KDIM;
      colbase = (bn - 8) * 256; dest = 1;
    } else {
      Bb = g_wv16 + (size_t)((bn - 10) * 256) * KDIM;
      colbase = (bn - 10) * 256; dest = 2;
    }
  } else {
    Ab = g_a16 + (size_t)(bm * 128) * KDIM;
    Bb = g_wo16 + (size_t)(bn * 256) * KDIM;
    colbase = bn * 256; dest = 3;
  }

  float ac[4][4][4];
#pragma unroll
  for (int mt = 0; mt < 4; mt++)
#pragma unroll
    for (int nt = 0; nt < 4; nt++)
#pragma unroll
      for (int q = 0; q < 4; q++) ac[mt][nt][q] = 0.f;

  auto issue = [&](int s, int k0) {
    const uint32_t st = smb + s * STG;
#pragma unroll
    for (int i = 0; i < 2; i++) {
      int e = i * 512 + tid;
      int r = e >> 3, c = e & 7;
      size_t go = (size_t)r * KDIM + k0 + c * 8;
      uint32_t so = (uint32_t)(r * GP + c * 16);
      cp16(st + so, Ab + go);
    }
#pragma unroll
    for (int i = 0; i < 4; i++) {
      int e = i * 512 + tid;
      int r = e >> 3, c = e & 7;
      size_t go = (size_t)r * KDIM + k0 + c * 8;
      uint32_t so = (uint32_t)(r * GP + c * 16);
      cp16(st + A_MAT + so, Bb + go);
    }
  };

  auto compute = [&](int s) {
    const uint32_t base = smb + s * STG;
#pragma unroll
    for (int ks = 0; ks < 4; ks++) {
      uint32_t af[4][4];
#pragma unroll
      for (int mt = 0; mt < 4; mt++) {
        uint32_t addr = base +
                        (uint32_t)(wm * 64 + mt * 16 + (i4 & 1) * 8 + j8) * GP +
                        (uint32_t)((i4 >> 1) * 8 + ks * 16) * 2;
        ldsm4(addr, af[mt]);
      }
      uint32_t bf[4][2];
#pragma unroll
      for (int p = 0; p < 2; p++) {
        uint32_t r[4];
        uint32_t addr = base + A_MAT +
                        (uint32_t)(wn * 32 + p * 16 + (i4 >> 1) * 8 + j8) * GP +
                        (uint32_t)((i4 & 1) * 8 + ks * 16) * 2;
        ldsm4(addr, r);
        bf[2 * p][0] = r[0]; bf[2 * p][1] = r[1];
        bf[2 * p + 1][0] = r[2]; bf[2 * p + 1][1] = r[3];
      }
#pragma unroll
      for (int mt = 0; mt < 4; mt++)
#pragma unroll
        for (int nt = 0; nt < 4; nt++)
          mmaf16(ac[mt][nt], af[mt], bf[nt][0], bf[nt][1]);
    }
  };

  const int KS = KDIM >> 6;  // 32
  issue(0, 0); cp_commit();
  issue(1, 64); cp_commit();

  for (int it = 0; it < KS; it++) {
    const int s = it % 3;
    cp_wait1();
    __syncthreads();
    if (it + 2 < KS) issue((it + 2) % 3, (it + 2) * 64);
    cp_commit();
    compute(s);
  }

  // epilogue
#pragma unroll
  for (int mt = 0; mt < 4; mt++)
#pragma unroll
    for (int nt = 0; nt < 4; nt++) {
      int row = bm * 128 + wm * 64 + mt * 16 + (lane >> 2);
      int col = colbase + wn * 32 + nt * 8 + (lane & 3) * 2;
      if (dest == 0) {
        float* c0 = g_q + (size_t)row * 2048 + col;
        *(float2*)c0 = make_float2(ac[mt][nt][0], ac[mt][nt][1]);
        *(float2*)(c0 + 8 * 2048) = make_float2(ac[mt][nt][2], ac[mt][nt][3]);
      } else if (dest == 1) {
        float* c0 = g_k + (size_t)row * 512 + col;
        *(float2*)c0 = make_float2(ac[mt][nt][0], ac[mt][nt][1]);
        *(float2*)(c0 + 8 * 512) = make_float2(ac[mt][nt][2], ac[mt][nt][3]);
      } else if (dest == 2) {
        size_t i0 = (size_t)row * 512 + col;
        size_t i1 = i0 + 8 * 512;
        __half2 v0 = __float22half2_rn(make_float2(ac[mt][nt][0], ac[mt][nt][1]));
        __half2 v1 = __float22half2_rn(make_float2(ac[mt][nt][2], ac[mt][nt][3]));
        *(__half2*)(g_v16 + i0) = v0;
        *(__half2*)(g_v16 + i1) = v1;
      } else {
        float* c0 = outC + (size_t)row * 2048 + col;
        *(float2*)c0 = make_float2(ac[mt][nt][0], ac[mt][nt][1]);
        *(float2*)(c0 + 8 * 2048) = make_float2(ac[mt][nt][2], ac[mt][nt][3]);
      }
    }
}

// =============== RoPE + RMSNorm -> single fp16 (merged q+k) =================
#define QW_TOT (MTOK * NH_)
#define KW_TOT (MTOK * NKV_)

__global__ __launch_bounds__(256) void rope_rms_f16(
    const float* __restrict__ qw, const float* __restrict__ kw) {
  int gw = (blockIdx.x * blockDim.x + threadIdx.x) >> 5;
  if (gw >= QW_TOT + KW_TOT) return;
  int lane = threadIdx.x & 31;
  const float* x;
  const float* w;
  __half* y;
  float osc;
  int lw, nh;
  if (gw < QW_TOT) {
    lw = gw; nh = NH_; x = g_q; w = qw; y = g_q16;
    osc = 0.08838834764831845f;  // 1/sqrt(128)
  } else {
    lw = gw - QW_TOT; nh = NKV_; x = g_k; w = kw; y = g_k16;
    osc = 1.0f;
  }
  int token = lw / nh;
  int s = token & (Ss_ - 1);
  const float* p = x + (size_t)lw * HD_;

  const float neg_l2theta_over_half = -13.287712379549449f / 64.f;
  float vals[4];
  float ss = 0.f;
#pragma unroll
  for (int hh = 0; hh < 2; hh++) {
    int d = lane + hh * 32;
    float x1 = p[d];
    float x2 = p[d + 64];
    float invf = exp2f((float)d * neg_l2theta_over_half);
    float ang = (float)s * invf;
    float c, sn;
    sincosf(ang, &sn, &c);
    float o1 = x1 * c - x2 * sn;
    float o2 = x2 * c + x1 * sn;
    vals[hh * 2] = o1;
    vals[hh * 2 + 1] = o2;
    ss += o1 * o1 + o2 * o2;
  }
#pragma unroll
  for (int o = 16; o >= 1; o >>= 1) ss += __shfl_xor_sync(0xffffffffu, ss, o);
  float r = rsqrtf(ss * (1.f / 128.f) + 1e-6f) * osc;
#pragma unroll
  for (int hh = 0; hh < 2; hh++) {
    int d = lane + hh * 32;
    size_t base = (size_t)lw * HD_;
    y[base + d] = __float2half_rn(vals[hh * 2] * r * w[d]);
    y[base + d + 64] = __float2half_rn(vals[hh * 2 + 1] * r * w[d + 64]);
  }
}

// == Flash attention: 296-CTA balanced schedule (LPT pairing) ================
// Tiles: 512 = 16 qt x 32 bh. Cost(qt) = 2qt+2 chunks.
// CTA 0..79: single expensive tile (qt15 x32, qt14 x32, qt13 bh0..15).
// CTA 80..295: pair (r, 431-r) from remaining 432 tiles sorted by cost desc.
#define FPITCH 272
#define FQ 0
#define KVSTG (128 * FPITCH)              // 34816 (K 64 rows + V 64 rows)
#define FKV0 (128 * FPITCH)
#define FKV1 (FKV0 + KVSTG)
#define FA2_SMEM (FKV1 + KVSTG)           // 104448 B -> 2 CTAs/SM
#define KOFF 0
#define VOFF (64 * FPITCH)
#define SM_OFF 4.0f

__device__ __forceinline__ void decode_rtile(int r, int& qt, int& bh) {
  // remaining tiles sorted by cost descending
  if (r < 16) { qt = 13; bh = 16 + r; }
  else { int rr = r - 16; qt = 12 - (rr >> 5); bh = rr & 31; }
}

__global__ __launch_bounds__(256, 2) void flash_attn_f16() {
  extern __shared__ char sm[];
  const uint32_t smb = smem_u32(sm);
  const int cid = blockIdx.x;
  const int tid = threadIdx.x, wid = tid >> 5, lane = tid & 31;
  const int i4 = lane >> 3, j8 = lane & 7;

  // ---- work-list decode ----
  int ntile, qts[2], bhs[2];
  if (cid < 80) {
    ntile = 1;
    if (cid < 64) { qts[0] = 15 - (cid >> 5); bhs[0] = cid & 31; }
    else          { qts[0] = 13; bhs[0] = cid - 64; }
  } else {
    ntile = 2;
    int j = cid - 80;
    decode_rtile(j, qts[0], bhs[0]);
    decode_rtile(431 - j, qts[1], bhs[1]);
  }

  const uint32_t qa_off = (uint32_t)(wid * 16 + (i4 & 1) * 8 + j8) * FPITCH +
                          (uint32_t)((i4 >> 1) * 8) * 2;
  const uint32_t kb_row = (uint32_t)((i4 >> 1) * 8 + j8);
  const uint32_t kb_koff = (uint32_t)((i4 & 1) * 8) * 2;
  const uint32_t v_kv = (uint32_t)((i4 & 1) * 8 + j8);
  const uint32_t v_d = (uint32_t)((i4 >> 1) * 8);
  const int krow = tid >> 2, kqtr = tid & 3;
  const uint32_t kv_smem_off = (uint32_t)(krow * FPITCH + kqtr * 64);

  for (int ti = 0; ti < ntile; ti++) {
    const int qt = qts[ti];
    const int b = bhs[ti] >> 4;
    const int h = bhs[ti] & 15;
    const int kvh = h >> 2;
    const int qb = qt * 128;
    const int qwb = qb + wid * 16;
    const int nkv = 2 * qt + 2;
    const size_t kv_lane_off = (size_t)krow * (NKV_ * HD_) + kvh * HD_ +
                               kqtr * 32;

    __syncthreads();  // previous tile fully done with all smem

    // start chunk 0 load
    {
      const uint32_t st = smb + FKV0 + kv_smem_off;
      const size_t gb = (size_t)(b * Ss_) * (NKV_ * HD_) + kv_lane_off;
#pragma unroll
      for (int q = 0; q < 4; q++) {
        cp16(st + KOFF + q * 16, g_k16 + gb + q * 8);
        cp16(st + VOFF + q * 16, g_v16 + gb + q * 8);
      }
    }
    cp_commit();

    // Q -> smem (overlaps cp.async latency)
    {
      const int row = tid >> 1, half = tid & 1;
      const size_t gof = (size_t)(b * Ss_ + qb + row) * (NH_ * HD_) + h * HD_ +
                         half * 64;
      const uint4* sq = (const uint4*)(g_q16 + gof);
      char* dq = sm + FQ + row * FPITCH + half * 128;
#pragma unroll
      for (int q = 0; q < 8; q++) *(uint4*)(dq + q * 16) = sq[q];
    }

    float oa[16][4];
#pragma unroll
    for (int nt = 0; nt < 16; nt++)
#pragma unroll
      for (int q = 0; q < 4; q++) oa[nt][q] = 0.f;
    float l0 = 0.f, l1 = 0.f;

    for (int kvi = 0; kvi < nkv; kvi++) {
      const int kvb = kvi * 64;
      const uint32_t buf = smb + ((kvi & 1) ? FKV1 : FKV0);

      if (kvi) __syncthreads();
      if (kvi + 1 < nkv) {
        const uint32_t st = smb + (((kvi + 1) & 1) ? FKV1 : FKV0) + kv_smem_off;
        const size_t gb = (size_t)(b * Ss_ + kvb + 64) * (NKV_ * HD_) +
                          kv_lane_off;
#pragma unroll
        for (int q = 0; q < 4; q++) {
          cp16(st + KOFF + q * 16, g_k16 + gb + q * 8);
          cp16(st + VOFF + q * 16, g_v16 + gb + q * 8);
        }
        cp_commit();
        cp_wait1();
      } else {
        cp_wait0();
      }
      __syncthreads();

      if (kvb > qwb + 15) continue;

      float s4[8][4];
#pragma unroll
      for (int j = 0; j < 8; j++)
#pragma unroll
        for (int q = 0; q < 4; q++) s4[j][q] = 0.f;

#pragma unroll
      for (int kt = 0; kt < 8; kt++) {
        uint32_t aQ[4];
        ldsm4(smb + FQ + qa_off + kt * 32, aQ);
#pragma unroll
        for (int p = 0; p < 4; p++) {
          uint32_t rK[4];
          uint32_t ka = (uint32_t)(p * 16) * FPITCH + kb_row * FPITCH +
                        kb_koff + (uint32_t)(kt * 32);
          ldsm4(buf + KOFF + ka, rK);
          mmaf16(s4[2 * p],     aQ, rK[0], rK[1]);
          mmaf16(s4[2 * p + 1], aQ, rK[2], rK[3]);
        }
      }

      if (kvb + 63 > qwb) {
        const int qr0 = qwb + (lane >> 2), qr1 = qr0 + 8;
        const int kc0 = kvb + (lane & 3) * 2;
#pragma unroll
        for (int j = 0; j < 8; j++) {
          int kv0 = kc0 + j * 8, kv1 = kv0 + 1;
          if (kv0 > qr0) s4[j][0] = -1e30f;
          if (kv1 > qr0) s4[j][1] = -1e30f;
          if (kv0 > qr1) s4[j][2] = -1e30f;
          if (kv1 > qr1) s4[j][3] = -1e30f;
        }
      }

      float sum0 = 0.f, sum1 = 0.f;
#pragma unroll
      for (int j = 0; j < 8; j++) {
        s4[j][0] = __expf(s4[j][0] - SM_OFF);
        s4[j][1] = __expf(s4[j][1] - SM_OFF);
        s4[j][2] = __expf(s4[j][2] - SM_OFF);
        s4[j][3] = __expf(s4[j][3] - SM_OFF);
        sum0 += s4[j][0] + s4[j][1];
        sum1 += s4[j][2] + s4[j][3];
      }
      sum0 += __shfl_xor_sync(0xffffffffu, sum0, 1);
      sum0 += __shfl_xor_sync(0xffffffffu, sum0, 2);
      sum1 += __shfl_xor_sync(0xffffffffu, sum1, 1);
      sum1 += __shfl_xor_sync(0xffffffffu, sum1, 2);
      l0 += sum0;
      l1 += sum1;

#pragma unroll
      for (int kt = 0; kt < 4; kt++) {
        uint32_t aP[4];
        {
          __half2 p0 = __float22half2_rn(
              make_float2(s4[2 * kt][0], s4[2 * kt][1]));
          __half2 p1 = __float22half2_rn(
              make_float2(s4[2 * kt][2], s4[2 * kt][3]));
          __half2 p2 = __float22half2_rn(
              make_float2(s4[2 * kt + 1][0], s4[2 * kt + 1][1]));
          __half2 p3 = __float22half2_rn(
              make_float2(s4[2 * kt + 1][2], s4[2 * kt + 1][3]));
          aP[0] = *reinterpret_cast<uint32_t*>(&p0);
          aP[1] = *reinterpret_cast<uint32_t*>(&p1);
          aP[2] = *reinterpret_cast<uint32_t*>(&p2);
          aP[3] = *reinterpret_cast<uint32_t*>(&p3);
        }
#pragma unroll
        for (int p = 0; p < 8; p++) {
          uint32_t rV[4];
          uint32_t va = (uint32_t)(kt * 16 + v_kv) * FPITCH +
                        (uint32_t)(p * 16 + v_d) * 2;
          ldsm4t(buf + VOFF + va, rV);
          mmaf16(oa[2 * p],     aP, rV[0], rV[1]);
          mmaf16(oa[2 * p + 1], aP, rV[2], rV[3]);
        }
      }
    }

    const float inv0 = 1.0f / l0, inv1 = 1.0f / l1;
    const int r0 = qwb + (lane >> 2);
#pragma unroll
    for (int nt = 0; nt < 16; nt++) {
      int col = h * HD_ + nt * 8 + (lane & 3) * 2;
      size_t idx0 = (size_t)(b * Ss_ + r0) * (NH_ * HD_) + col;
      size_t idx1 = (size_t)(b * Ss_ + r0 + 8) * (NH_ * HD_) + col;
      __half2 o0 = __float22half2_rn(make_float2(oa[nt][0] * inv0,
                                                 oa[nt][1] * inv0));
      __half2 o1 = __float22half2_rn(make_float2(oa[nt][2] * inv1,
                                                 oa[nt][3] * inv1));
      *(__half2*)(g_a16 + idx0) = o0;
      *(__half2*)(g_a16 + idx1) = o1;
    }
  }
}

// ============================ launch ========================================
extern "C" void kernel_launch(void* const* d_in, const int* in_sizes, int n_in,
                              void* d_out, int out_size) {
  const float* hs = (const float*)d_in[0];
  const float* wq = (const float*)d_in[1];
  const float* wk = (const float*)d_in[2];
  const float* wv = (const float*)d_in[3];
  const float* wo = (const float*)d_in[4];
  const float* qw = (const float*)d_in[5];
  const float* kw = (const float*)d_in[6];
  float* out = (float*)d_out;

  cudaFuncSetAttribute(gemm_f16, cudaFuncAttributeMaxDynamicSharedMemorySize,
                       GSM);
  cudaFuncSetAttribute(flash_attn_f16,
                       cudaFuncAttributeMaxDynamicSharedMemorySize, FA2_SMEM);

  // merged prep: fp16 rounding of hs + all weights
  round_all<<<(N4_TOT + 255) / 256, 256>>>(hs, wq, wk, wv, wo);

  // Fused Q+K+V projections (fp16 1-pass, BK=64)
  gemm_f16<<<dim3(12, MTOK / 128), 512, GSM>>>(0, nullptr);

  // RoPE + RMSNorm (merged q+k; q pre-scaled by 1/sqrt(HD))
  rope_rms_f16<<<((QW_TOT + KW_TOT) * 32 + 255) / 256, 256>>>(qw, kw);

  // Flash attention, 296-CTA balanced schedule (2 CTAs on every SM)
  flash_attn_f16<<<296, 256, FA2_SMEM>>>();

  // Output projection (fp16 1-pass, BK=64) -> d_out
  gemm_f16<<<dim3(Hh_ / 256, MTOK / 128), 512, GSM>>>(1, out);
}

// round 17
// speedup vs baseline: 1.1591x; 1.0037x over previous
#include <cuda_runtime.h>
#include <cuda_fp16.h>
#include <math.h>
#include <stdint.h>

#define Bb_ 2
#define Ss_ 2048
#define Hh_ 2048
#define NH_ 16
#define NKV_ 4
#define HD_ 128
#define MTOK (Bb_ * Ss_)   // 4096 tokens

// Scratch (allocation-free rule: __device__ globals)
__device__ float g_q[(size_t)MTOK * NH_ * HD_];    // fp32 pre-rope Q
__device__ float g_k[(size_t)MTOK * NKV_ * HD_];   // fp32 pre-rope K
// fp16 GEMM operands (single-rounded)
__device__ __half g_hs16[(size_t)MTOK * Hh_];
__device__ __half g_wq16[(size_t)NH_ * HD_ * Hh_];
__device__ __half g_wk16[(size_t)NKV_ * HD_ * Hh_];
__device__ __half g_wv16[(size_t)NKV_ * HD_ * Hh_];
// attention inputs (fp16, single)
__device__ __half g_q16[(size_t)MTOK * NH_ * HD_];
__device__ __half g_k16[(size_t)MTOK * NKV_ * HD_];
__device__ __half g_v16[(size_t)MTOK * NKV_ * HD_];
// O-proj operands (fp16 1-pass)
__device__ __half g_wo16[(size_t)Hh_ * NH_ * HD_];
__device__ __half g_a16[(size_t)MTOK * NH_ * HD_];

// ============================ helpers =======================================
__device__ __forceinline__ uint32_t smem_u32(const void* p) {
  uint32_t a;
  asm("{ .reg .u64 t; cvta.to.shared.u64 t, %1; cvt.u32.u64 %0, t; }"
      : "=r"(a) : "l"(p));
  return a;
}
__device__ __forceinline__ void cp16(uint32_t dst, const void* src) {
  asm volatile("cp.async.cg.shared.global [%0], [%1], 16;"
               :: "r"(dst), "l"(src));
}
__device__ __forceinline__ void cp_commit() {
  asm volatile("cp.async.commit_group;" ::: "memory");
}
__device__ __forceinline__ void cp_wait1() {
  asm volatile("cp.async.wait_group 1;" ::: "memory");
}
__device__ __forceinline__ void cp_wait0() {
  asm volatile("cp.async.wait_group 0;" ::: "memory");
}
__device__ __forceinline__ void ldsm4(uint32_t addr, uint32_t r[4]) {
  asm volatile("ldmatrix.sync.aligned.m8n8.x4.shared.b16 {%0,%1,%2,%3}, [%4];"
               : "=r"(r[0]), "=r"(r[1]), "=r"(r[2]), "=r"(r[3]) : "r"(addr));
}
__device__ __forceinline__ void ldsm4t(uint32_t addr, uint32_t r[4]) {
  asm volatile(
      "ldmatrix.sync.aligned.m8n8.x4.trans.shared.b16 {%0,%1,%2,%3}, [%4];"
      : "=r"(r[0]), "=r"(r[1]), "=r"(r[2]), "=r"(r[3]) : "r"(addr));
}
__device__ __forceinline__ void mmaf16(float c[4], const uint32_t a[4],
                                       uint32_t b0, uint32_t b1) {
  asm volatile(
      "mma.sync.aligned.m16n8k16.row.col.f32.f16.f16.f32 "
      "{%0,%1,%2,%3}, {%4,%5,%6,%7}, {%8,%9}, {%0,%1,%2,%3};"
      : "+f"(c[0]), "+f"(c[1]), "+f"(c[2]), "+f"(c[3])
      : "r"(a[0]), "r"(a[1]), "r"(a[2]), "r"(a[3]), "r"(b0), "r"(b1));
}

// ============================ prep kernel (merged, 4x ILP) ==================
#define N4_HS (MTOK * Hh_ / 4)            // 2M
#define N4_WQ (NH_ * HD_ * Hh_ / 4)       // 1M
#define N4_WKV (NKV_ * HD_ * Hh_ / 4)     // 256K
#define N4_TOT (N4_HS + N4_WQ + 2 * N4_WKV + N4_WQ)
#define PREP_Q ((N4_TOT + 3) / 4)

__global__ __launch_bounds__(256) void round_all(
    const float* __restrict__ hs, const float* __restrict__ wq,
    const float* __restrict__ wk, const float* __restrict__ wv,
    const float* __restrict__ wo) {
  const int t = blockIdx.x * blockDim.x + threadIdx.x;
#pragma unroll
  for (int u = 0; u < 4; u++) {
    int i = t + u * PREP_Q;
    if (i >= N4_TOT) break;
    const float* src;
    __half* dst;
    int off;
    if (i < N4_HS) {
      src = hs; dst = g_hs16; off = i;
    } else if (i < N4_HS + N4_WQ) {
      src = wq; dst = g_wq16; off = i - N4_HS;
    } else if (i < N4_HS + N4_WQ + N4_WKV) {
      src = wk; dst = g_wk16; off = i - N4_HS - N4_WQ;
    } else if (i < N4_HS + N4_WQ + 2 * N4_WKV) {
      src = wv; dst = g_wv16; off = i - N4_HS - N4_WQ - N4_WKV;
    } else {
      src = wo; dst = g_wo16; off = i - N4_HS - N4_WQ - 2 * N4_WKV;
    }
    float4 v = ((const float4*)src)[off];
    __half2 a = __float22half2_rn(make_float2(v.x, v.y));
    __half2 b = __float22half2_rn(make_float2(v.z, v.w));
    ((uint2*)dst)[off] = make_uint2(*reinterpret_cast<uint32_t*>(&a),
                                    *reinterpret_cast<uint32_t*>(&b));
  }
}

// ====== fp16 1-pass GEMM, BK=64, cp.async 3-stage, 512 threads ==============
#define GP 144
#define A_MAT (128 * GP)            // 18432 B
#define B_MAT (256 * GP)            // 36864 B
#define STG (A_MAT + B_MAT)         // 55296 B
#define GSM (3 * STG)               // 165888 B
#define KDIM 2048

// mode 0: fused QKV (bn<8 Q fp32, 8..9 K fp32, 10..11 V fp16)
// mode 1: O proj (A = g_a16, B = g_wo16, C = outC fp32)
__global__ __launch_bounds__(512, 1) void gemm_f16(int mode, float* outC) {
  extern __shared__ char sm[];
  const uint32_t smb = smem_u32(sm);
  const int tid = threadIdx.x, wid = tid >> 5, lane = tid & 31;
  const int wm = wid & 1, wn = wid >> 1;
  const int bn = blockIdx.x, bm = blockIdx.y;
  const int i4 = lane >> 3, j8 = lane & 7;

  const __half *Ab, *Bb;
  int colbase, dest;  // 0=Q fp32, 1=K fp32, 2=V fp16, 3=out fp32
  if (mode == 0) {
    Ab = g_hs16 + (size_t)(bm * 128) * KDIM;
    if (bn < 8) {
      Bb = g_wq16 + (size_t)(bn * 256) * KDIM;
      colbase = bn * 256; dest = 0;
    } else if (bn < 10) {
      Bb = g_wk16 + (size_t)((bn - 8) * 256) * KDIM;
      colbase = (bn - 8) * 256; dest = 1;
    } else {
      Bb = g_wv16 + (size_t)((bn - 10) * 256) * KDIM;
      colbase = (bn - 10) * 256; dest = 2;
    }
  } else {
    Ab = g_a16 + (size_t)(bm * 128) * KDIM;
    Bb = g_wo16 + (size_t)(bn * 256) * KDIM;
    colbase = bn * 256; dest = 3;
  }

  float ac[4][4][4];
#pragma unroll
  for (int mt = 0; mt < 4; mt++)
#pragma unroll
    for (int nt = 0; nt < 4; nt++)
#pragma unroll
      for (int q = 0; q < 4; q++) ac[mt][nt][q] = 0.f;

  auto issue = [&](int s, int k0) {
    const uint32_t st = smb + s * STG;
#pragma unroll
    for (int i = 0; i < 2; i++) {
      int e = i * 512 + tid;
      int r = e >> 3, c = e & 7;
      size_t go = (size_t)r * KDIM + k0 + c * 8;
      uint32_t so = (uint32_t)(r * GP + c * 16);
      cp16(st + so, Ab + go);
    }
#pragma unroll
    for (int i = 0; i < 4; i++) {
      int e = i * 512 + tid;
      int r = e >> 3, c = e & 7;
      size_t go = (size_t)r * KDIM + k0 + c * 8;
      uint32_t so = (uint32_t)(r * GP + c * 16);
      cp16(st + A_MAT + so, Bb + go);
    }
  };

  auto compute = [&](int s) {
    const uint32_t base = smb + s * STG;
#pragma unroll
    for (int ks = 0; ks < 4; ks++) {
      uint32_t af[4][4];
#pragma unroll
      for (int mt = 0; mt < 4; mt++) {
        uint32_t addr = base +
                        (uint32_t)(wm * 64 + mt * 16 + (i4 & 1) * 8 + j8) * GP +
                        (uint32_t)((i4 >> 1) * 8 + ks * 16) * 2;
        ldsm4(addr, af[mt]);
      }
      uint32_t bf[4][2];
#pragma unroll
      for (int p = 0; p < 2; p++) {
        uint32_t r[4];
        uint32_t addr = base + A_MAT +
                        (uint32_t)(wn * 32 + p * 16 + (i4 >> 1) * 8 + j8) * GP +
                        (uint32_t)((i4 & 1) * 8 + ks * 16) * 2;
        ldsm4(addr, r);
        bf[2 * p][0] = r[0]; bf[2 * p][1] = r[1];
        bf[2 * p + 1][0] = r[2]; bf[2 * p + 1][1] = r[3];
      }
#pragma unroll
      for (int mt = 0; mt < 4; mt++)
#pragma unroll
        for (int nt = 0; nt < 4; nt++)
          mmaf16(ac[mt][nt], af[mt], bf[nt][0], bf[nt][1]);
    }
  };

  const int KS = KDIM >> 6;  // 32
  issue(0, 0); cp_commit();
  issue(1, 64); cp_commit();

  for (int it = 0; it < KS; it++) {
    const int s = it % 3;
    cp_wait1();
    __syncthreads();
    if (it + 2 < KS) issue((it + 2) % 3, (it + 2) * 64);
    cp_commit();
    compute(s);
  }

  // epilogue
#pragma unroll
  for (int mt = 0; mt < 4; mt++)
#pragma unroll
    for (int nt = 0; nt < 4; nt++) {
      int row = bm * 128 + wm * 64 + mt * 16 + (lane >> 2);
      int col = colbase + wn * 32 + nt * 8 + (lane & 3) * 2;
      if (dest == 0) {
        float* c0 = g_q + (size_t)row * 2048 + col;
        *(float2*)c0 = make_float2(ac[mt][nt][0], ac[mt][nt][1]);
        *(float2*)(c0 + 8 * 2048) = make_float2(ac[mt][nt][2], ac[mt][nt][3]);
      } else if (dest == 1) {
        float* c0 = g_k + (size_t)row * 512 + col;
        *(float2*)c0 = make_float2(ac[mt][nt][0], ac[mt][nt][1]);
        *(float2*)(c0 + 8 * 512) = make_float2(ac[mt][nt][2], ac[mt][nt][3]);
      } else if (dest == 2) {
        size_t i0 = (size_t)row * 512 + col;
        size_t i1 = i0 + 8 * 512;
        __half2 v0 = __float22half2_rn(make_float2(ac[mt][nt][0], ac[mt][nt][1]));
        __half2 v1 = __float22half2_rn(make_float2(ac[mt][nt][2], ac[mt][nt][3]));
        *(__half2*)(g_v16 + i0) = v0;
        *(__half2*)(g_v16 + i1) = v1;
      } else {
        float* c0 = outC + (size_t)row * 2048 + col;
        *(float2*)c0 = make_float2(ac[mt][nt][0], ac[mt][nt][1]);
        *(float2*)(c0 + 8 * 2048) = make_float2(ac[mt][nt][2], ac[mt][nt][3]);
      }
    }
}

// ====== RoPE + RMSNorm -> single fp16 (merged q+k, vectorized) ==============
#define QW_TOT (MTOK * NH_)
#define KW_TOT (MTOK * NKV_)

__global__ __launch_bounds__(256) void rope_rms_f16(
    const float* __restrict__ qw, const float* __restrict__ kw) {
  int gw = (blockIdx.x * blockDim.x + threadIdx.x) >> 5;
  if (gw >= QW_TOT + KW_TOT) return;
  int lane = threadIdx.x & 31;
  const float* x;
  const float* w;
  __half* y;
  float osc;
  int lw, nh;
  if (gw < QW_TOT) {
    lw = gw; nh = NH_; x = g_q; w = qw; y = g_q16;
    osc = 0.08838834764831845f;  // 1/sqrt(128)
  } else {
    lw = gw - QW_TOT; nh = NKV_; x = g_k; w = kw; y = g_k16;
    osc = 1.0f;
  }
  int token = lw / nh;
  int s = token & (Ss_ - 1);
  const float2* p2 = (const float2*)(x + (size_t)lw * HD_);

  // lane covers d0 = 2*lane, d0+1 (paired with d0+64, d0+65)
  float2 x1 = p2[lane];
  float2 x2 = p2[lane + 32];

  const float neg_l2theta_over_half = -13.287712379549449f / 64.f;
  int d0 = lane * 2;
  float inv0 = exp2f((float)d0 * neg_l2theta_over_half);
  float inv1 = exp2f((float)(d0 + 1) * neg_l2theta_over_half);
  float c0, s0, c1, s1;
  sincosf((float)s * inv0, &s0, &c0);
  sincosf((float)s * inv1, &s1, &c1);

  float o1x = x1.x * c0 - x2.x * s0;
  float o1y = x1.y * c1 - x2.y * s1;
  float o2x = x2.x * c0 + x1.x * s0;
  float o2y = x2.y * c1 + x1.y * s1;

  float ss = o1x * o1x + o1y * o1y + o2x * o2x + o2y * o2y;
#pragma unroll
  for (int o = 16; o >= 1; o >>= 1) ss += __shfl_xor_sync(0xffffffffu, ss, o);
  float r = rsqrtf(ss * (1.f / 128.f) + 1e-6f) * osc;

  float2 w1 = ((const float2*)w)[lane];
  float2 w2 = ((const float2*)w)[lane + 32];
  __half2* y2 = (__half2*)(y + (size_t)lw * HD_);
  y2[lane] = __float22half2_rn(make_float2(o1x * r * w1.x, o1y * r * w1.y));
  y2[lane + 32] =
      __float22half2_rn(make_float2(o2x * r * w2.x, o2y * r * w2.y));
}

// == Flash attention: 296-CTA balanced schedule (LPT pairing) ================
#define FPITCH 272
#define FQ 0
#define KVSTG (128 * FPITCH)              // 34816 (K 64 rows + V 64 rows)
#define FKV0 (128 * FPITCH)
#define FKV1 (FKV0 + KVSTG)
#define FA2_SMEM (FKV1 + KVSTG)           // 104448 B -> 2 CTAs/SM
#define KOFF 0
#define VOFF (64 * FPITCH)
#define SM_OFF 4.0f

__device__ __forceinline__ void decode_rtile(int r, int& qt, int& bh) {
  if (r < 16) { qt = 13; bh = 16 + r; }
  else { int rr = r - 16; qt = 12 - (rr >> 5); bh = rr & 31; }
}

__global__ __launch_bounds__(256, 2) void flash_attn_f16() {
  extern __shared__ char sm[];
  const uint32_t smb = smem_u32(sm);
  const int cid = blockIdx.x;
  const int tid = threadIdx.x, wid = tid >> 5, lane = tid & 31;
  const int i4 = lane >> 3, j8 = lane & 7;

  int ntile, qts[2], bhs[2];
  if (cid < 80) {
    ntile = 1;
    if (cid < 64) { qts[0] = 15 - (cid >> 5); bhs[0] = cid & 31; }
    else          { qts[0] = 13; bhs[0] = cid - 64; }
  } else {
    ntile = 2;
    int j = cid - 80;
    decode_rtile(j, qts[0], bhs[0]);
    decode_rtile(431 - j, qts[1], bhs[1]);
  }

  const uint32_t qa_off = (uint32_t)(wid * 16 + (i4 & 1) * 8 + j8) * FPITCH +
                          (uint32_t)((i4 >> 1) * 8) * 2;
  const uint32_t kb_row = (uint32_t)((i4 >> 1) * 8 + j8);
  const uint32_t kb_koff = (uint32_t)((i4 & 1) * 8) * 2;
  const uint32_t v_kv = (uint32_t)((i4 & 1) * 8 + j8);
  const uint32_t v_d = (uint32_t)((i4 >> 1) * 8);
  const int krow = tid >> 2, kqtr = tid & 3;
  const uint32_t kv_smem_off = (uint32_t)(krow * FPITCH + kqtr * 64);

  for (int ti = 0; ti < ntile; ti++) {
    const int qt = qts[ti];
    const int b = bhs[ti] >> 4;
    const int h = bhs[ti] & 15;
    const int kvh = h >> 2;
    const int qb = qt * 128;
    const int qwb = qb + wid * 16;
    const int nkv = 2 * qt + 2;
    const size_t kv_lane_off = (size_t)krow * (NKV_ * HD_) + kvh * HD_ +
                               kqtr * 32;

    __syncthreads();

    {
      const uint32_t st = smb + FKV0 + kv_smem_off;
      const size_t gb = (size_t)(b * Ss_) * (NKV_ * HD_) + kv_lane_off;
#pragma unroll
      for (int q = 0; q < 4; q++) {
        cp16(st + KOFF + q * 16, g_k16 + gb + q * 8);
        cp16(st + VOFF + q * 16, g_v16 + gb + q * 8);
      }
    }
    cp_commit();

    {
      const int row = tid >> 1, half = tid & 1;
      const size_t gof = (size_t)(b * Ss_ + qb + row) * (NH_ * HD_) + h * HD_ +
                         half * 64;
      const uint4* sq = (const uint4*)(g_q16 + gof);
      char* dq = sm + FQ + row * FPITCH + half * 128;
#pragma unroll
      for (int q = 0; q < 8; q++) *(uint4*)(dq + q * 16) = sq[q];
    }

    float oa[16][4];
#pragma unroll
    for (int nt = 0; nt < 16; nt++)
#pragma unroll
      for (int q = 0; q < 4; q++) oa[nt][q] = 0.f;
    float l0 = 0.f, l1 = 0.f;

    for (int kvi = 0; kvi < nkv; kvi++) {
      const int kvb = kvi * 64;
      const uint32_t buf = smb + ((kvi & 1) ? FKV1 : FKV0);

      if (kvi) __syncthreads();
      if (kvi + 1 < nkv) {
        const uint32_t st = smb + (((kvi + 1) & 1) ? FKV1 : FKV0) + kv_smem_off;
        const size_t gb = (size_t)(b * Ss_ + kvb + 64) * (NKV_ * HD_) +
                          kv_lane_off;
#pragma unroll
        for (int q = 0; q < 4; q++) {
          cp16(st + KOFF + q * 16, g_k16 + gb + q * 8);
          cp16(st + VOFF + q * 16, g_v16 + gb + q * 8);
        }
        cp_commit();
        cp_wait1();
      } else {
        cp_wait0();
      }
      __syncthreads();

      if (kvb > qwb + 15) continue;

      float s4[8][4];
#pragma unroll
      for (int j = 0; j < 8; j++)
#pragma unroll
        for (int q = 0; q < 4; q++) s4[j][q] = 0.f;

#pragma unroll
      for (int kt = 0; kt < 8; kt++) {
        uint32_t aQ[4];
        ldsm4(smb + FQ + qa_off + kt * 32, aQ);
#pragma unroll
        for (int p = 0; p < 4; p++) {
          uint32_t rK[4];
          uint32_t ka = (uint32_t)(p * 16) * FPITCH + kb_row * FPITCH +
                        kb_koff + (uint32_t)(kt * 32);
          ldsm4(buf + KOFF + ka, rK);
          mmaf16(s4[2 * p],     aQ, rK[0], rK[1]);
          mmaf16(s4[2 * p + 1], aQ, rK[2], rK[3]);
        }
      }

      if (kvb + 63 > qwb) {
        const int qr0 = qwb + (lane >> 2), qr1 = qr0 + 8;
        const int kc0 = kvb + (lane & 3) * 2;
#pragma unroll
        for (int j = 0; j < 8; j++) {
          int kv0 = kc0 + j * 8, kv1 = kv0 + 1;
          if (kv0 > qr0) s4[j][0] = -1e30f;
          if (kv1 > qr0) s4[j][1] = -1e30f;
          if (kv0 > qr1) s4[j][2] = -1e30f;
          if (kv1 > qr1) s4[j][3] = -1e30f;
        }
      }

      float sum0 = 0.f, sum1 = 0.f;
#pragma unroll
      for (int j = 0; j < 8; j++) {
        s4[j][0] = __expf(s4[j][0] - SM_OFF);
        s4[j][1] = __expf(s4[j][1] - SM_OFF);
        s4[j][2] = __expf(s4[j][2] - SM_OFF);
        s4[j][3] = __expf(s4[j][3] - SM_OFF);
        sum0 += s4[j][0] + s4[j][1];
        sum1 += s4[j][2] + s4[j][3];
      }
      sum0 += __shfl_xor_sync(0xffffffffu, sum0, 1);
      sum0 += __shfl_xor_sync(0xffffffffu, sum0, 2);
      sum1 += __shfl_xor_sync(0xffffffffu, sum1, 1);
      sum1 += __shfl_xor_sync(0xffffffffu, sum1, 2);
      l0 += sum0;
      l1 += sum1;

#pragma unroll
      for (int kt = 0; kt < 4; kt++) {
        uint32_t aP[4];
        {
          __half2 p0 = __float22half2_rn(
              make_float2(s4[2 * kt][0], s4[2 * kt][1]));
          __half2 p1 = __float22half2_rn(
              make_float2(s4[2 * kt][2], s4[2 * kt][3]));
          __half2 p2 = __float22half2_rn(
              make_float2(s4[2 * kt + 1][0], s4[2 * kt + 1][1]));
          __half2 p3 = __float22half2_rn(
              make_float2(s4[2 * kt + 1][2], s4[2 * kt + 1][3]));
          aP[0] = *reinterpret_cast<uint32_t*>(&p0);
          aP[1] = *reinterpret_cast<uint32_t*>(&p1);
          aP[2] = *reinterpret_cast<uint32_t*>(&p2);
          aP[3] = *reinterpret_cast<uint32_t*>(&p3);
        }
#pragma unroll
        for (int p = 0; p < 8; p++) {
          uint32_t rV[4];
          uint32_t va = (uint32_t)(kt * 16 + v_kv) * FPITCH +
                        (uint32_t)(p * 16 + v_d) * 2;
          ldsm4t(buf + VOFF + va, rV);
          mmaf16(oa[2 * p],     aP, rV[0], rV[1]);
          mmaf16(oa[2 * p + 1], aP, rV[2], rV[3]);
        }
      }
    }

    const float inv0 = 1.0f / l0, inv1 = 1.0f / l1;
    const int r0 = qwb + (lane >> 2);
#pragma unroll
    for (int nt = 0; nt < 16; nt++) {
      int col = h * HD_ + nt * 8 + (lane & 3) * 2;
      size_t idx0 = (size_t)(b * Ss_ + r0) * (NH_ * HD_) + col;
      size_t idx1 = (size_t)(b * Ss_ + r0 + 8) * (NH_ * HD_) + col;
      __half2 o0 = __float22half2_rn(make_float2(oa[nt][0] * inv0,
                                                 oa[nt][1] * inv0));
      __half2 o1 = __float22half2_rn(make_float2(oa[nt][2] * inv1,
                                                 oa[nt][3] * inv1));
      *(__half2*)(g_a16 + idx0) = o0;
      *(__half2*)(g_a16 + idx1) = o1;
    }
  }
}

// ============================ launch ========================================
extern "C" void kernel_launch(void* const* d_in, const int* in_sizes, int n_in,
                              void* d_out, int out_size) {
  const float* hs = (const float*)d_in[0];
  const float* wq = (const float*)d_in[1];
  const float* wk = (const float*)d_in[2];
  const float* wv = (const float*)d_in[3];
  const float* wo = (const float*)d_in[4];
  const float* qw = (const float*)d_in[5];
  const float* kw = (const float*)d_in[6];
  float* out = (float*)d_out;

  cudaFuncSetAttribute(gemm_f16, cudaFuncAttributeMaxDynamicSharedMemorySize,
                       GSM);
  cudaFuncSetAttribute(flash_attn_f16,
                       cudaFuncAttributeMaxDynamicSharedMemorySize, FA2_SMEM);

  // merged prep (4x ILP): fp16 rounding of hs + all weights
  round_all<<<(PREP_Q + 255) / 256, 256>>>(hs, wq, wk, wv, wo);

  // Fused Q+K+V projections (fp16 1-pass, BK=64)
  gemm_f16<<<dim3(12, MTOK / 128), 512, GSM>>>(0, nullptr);

  // RoPE + RMSNorm (merged q+k, vectorized; q pre-scaled by 1/sqrt(HD))
  rope_rms_f16<<<((QW_TOT + KW_TOT) * 32 + 255) / 256, 256>>>(qw, kw);

  // Flash attention, 296-CTA balanced schedule
  flash_attn_f16<<<296, 256, FA2_SMEM>>>();

  // Output projection (fp16 1-pass, BK=64) -> d_out
  gemm_f16<<<dim3(Hh_ / 256, MTOK / 128), 512, GSM>>>(1, out);
}